// round 7
// baseline (speedup 1.0000x reference)
#include <cuda_runtime.h>
#include <cuda_pipeline.h>

#define B 32
#define M 32
#define C 1024
#define R 28
#define INV_R2 (1.0f / (R * R))

#define IMGS_PER_BLK 8
#define ROWS_PER_BLK (IMGS_PER_BLK * R)          // 224
#define FLOATS_PER_BLK (ROWS_PER_BLK * R)        // 6272
#define F4_PER_BLK (FLOATS_PER_BLK / 4)          // 1568
#define THREADS 224
#define F4_PER_THREAD (F4_PER_BLK / THREADS)     // 7
#define BLKS_PER_B (C / IMGS_PER_BLK)            // 128

// Scratch (allocation-free rule: __device__ global)
__device__ float g_col[B * M * R];   // column sums of Masks: (B, M, R)

// ---------------------------------------------------------------------------
// Kernel 1: col[b,m,j] = sum_i Masks[b,m,i,j].
// One thread per (b,m,j) = 28672 threads / 112 blocks (one wide wave).
// 28 independent stride-112B loads per thread (MLP=28), coalesced across j.
// ---------------------------------------------------------------------------
__global__ void reduce_M_kernel(const float* __restrict__ Mk) {
    int tid = blockIdx.x * blockDim.x + threadIdx.x;
    if (tid >= B * M * R) return;
    int j  = tid % R;
    int bm = tid / R;
    const float* p = Mk + (size_t)bm * R * R + j;
    float s = 0.0f;
#pragma unroll
    for (int i = 0; i < R; i++) s += __ldcs(p + i * R);
    g_col[tid] = s;
}

// ---------------------------------------------------------------------------
// Kernel 2 (fused, cp.async): stream the 8-image tile global->smem via
// LDGSTS (cp.async.cg, 16B): data never touches registers, so in-flight
// load depth is decoupled from the register file. Natural regs ~30 ->
// smem-limited residency of 7 blocks/SM (49 warps) WITH full load depth —
// the combination R1..R6 never achieved.
//
//  - cp.async: warp moves 512B contiguous per op, 7 ops back-to-back.
//  - read-back: thread t does 7x LDS.128 at byte 112t+16k; per 8-lane phase
//    the f4-bank-group is 7t mod 8 (permutation) -> conflict-free.
//  - einsum tail unchanged.
// ---------------------------------------------------------------------------
__global__ void fused_rowsum_einsum_kernel(const float* __restrict__ F,
                                           float* __restrict__ out) {
    __shared__ float tile[FLOATS_PER_BLK];    // 25088 B
    __shared__ float rowsum[ROWS_PER_BLK];    // 224 floats
    __shared__ float col_s[M * R];            // 896 floats

    const int tid = threadIdx.x;
    const int blk = blockIdx.x;
    const int b   = blk / BLKS_PER_B;

    // Kick off the async tile load FIRST (7 x 16B per thread, no data regs)
    const float4* src = reinterpret_cast<const float4*>(F) + (size_t)blk * F4_PER_BLK;
    float4* dst = reinterpret_cast<float4*>(tile);
#pragma unroll
    for (int k = 0; k < F4_PER_THREAD; k++)
        __pipeline_memcpy_async(&dst[k * THREADS + tid], &src[k * THREADS + tid], 16);
    __pipeline_commit();

    // Overlap: stage col[b] (L2-hot: 128 blocks share it) while tile flies
    {
        const float* cp = g_col + b * (M * R);
#pragma unroll
        for (int k = 0; k < 4; k++)
            col_s[k * THREADS + tid] = cp[k * THREADS + tid];
    }

    __pipeline_wait_prior(0);
    __syncthreads();

    // Row sums: thread t sums row t (7 x LDS.128, conflict-free permutation)
    {
        const float4* rp = reinterpret_cast<const float4*>(tile) + tid * (R / 4);
        float s = 0.0f;
#pragma unroll
        for (int k = 0; k < R / 4; k++) {
            float4 w = rp[k];
            s += (w.x + w.y) + (w.z + w.w);
        }
        rowsum[tid] = s;
    }
    __syncthreads();

    // Einsum tail: 256 outputs = 32 m x 8 c_local
    const int c0 = (blk % BLKS_PER_B) * IMGS_PER_BLK;
    for (int o = tid; o < M * IMGS_PER_BLK; o += THREADS) {
        int m  = o / IMGS_PER_BLK;
        int cl = o % IMGS_PER_BLK;
        float acc = 0.0f;
#pragma unroll
        for (int r = 0; r < R; r++)
            acc += col_s[m * R + r] * rowsum[cl * R + r];
        out[((size_t)b * M + m) * C + c0 + cl] = acc * INV_R2;
    }
}

extern "C" void kernel_launch(void* const* d_in, const int* in_sizes, int n_in,
                              void* d_out, int out_size) {
    const float* F  = (const float*)d_in[0];  // (B, C, R, R)
    const float* Mk = (const float*)d_in[1];  // (B, M, R, R)
    float* out = (float*)d_out;               // (B, M, C)

    {
        int n = B * M * R;  // 28672
        reduce_M_kernel<<<(n + 255) / 256, 256>>>(Mk);
    }
    {
        int nblks = (B * C) / IMGS_PER_BLK;   // 4096
        fused_rowsum_einsum_kernel<<<nblks, THREADS>>>(F, out);
    }
}